// round 10
// baseline (speedup 1.0000x reference)
#include <cuda_runtime.h>
#include <cuda_fp16.h>
#include <math.h>
#include <stdint.h>

// Problem constants
#define Bn 16
#define Sn 2048
#define Dn 128
#define TM 64           // y rows per CTA
#define TN 64           // x cols per tile
#define NT (Sn / TN)    // 32 tiles
#define RSB 272         // smem row stride bytes (136 halves): conflict-free ldmatrix
#define TILE_B (TM * RSB)   // 17408 bytes per 64x128 half tile

// ---------------------------------------------------------------------------
// Global scratch (referenced ONLY from device code)
// ---------------------------------------------------------------------------
__device__ float  g_ysum[Bn * Dn];
__device__ __half g_Yh[Bn * Sn * Dn];
__device__ __half g_Xh[Bn * Sn * Dn];
__device__ __half g_Xl[Bn * Sn * Dn];

// ---------------------------------------------------------------------------
// Helpers
// ---------------------------------------------------------------------------
__device__ __forceinline__ uint32_t smem_to_u32(const void* p) {
    uint32_t a;
    asm("{ .reg .u64 t; cvta.to.shared.u64 t, %1; cvt.u32.u64 %0, t; }" : "=r"(a) : "l"(p));
    return a;
}

#define CP16(dst, src) \
    asm volatile("cp.async.cg.shared.global [%0], [%1], 16;" :: "r"(dst), "l"(src))
#define CP_COMMIT() asm volatile("cp.async.commit_group;" ::: "memory")
#define CP_WAIT0()  asm volatile("cp.async.wait_group 0;" ::: "memory")

#define LDM4(r, a) \
    asm volatile("ldmatrix.sync.aligned.m8n8.x4.shared.b16 {%0,%1,%2,%3}, [%4];" \
                 : "=r"((r)[0]), "=r"((r)[1]), "=r"((r)[2]), "=r"((r)[3]) : "r"(a))
#define LDM4T(r, a) \
    asm volatile("ldmatrix.sync.aligned.m8n8.x4.trans.shared.b16 {%0,%1,%2,%3}, [%4];" \
                 : "=r"((r)[0]), "=r"((r)[1]), "=r"((r)[2]), "=r"((r)[3]) : "r"(a))

#define MMA16816(c, a, b0, b1) \
    asm volatile("mma.sync.aligned.m16n8k16.row.col.f32.f16.f16.f32 " \
                 "{%0,%1,%2,%3},{%4,%5,%6,%7},{%8,%9},{%0,%1,%2,%3};" \
                 : "+f"((c)[0]), "+f"((c)[1]), "+f"((c)[2]), "+f"((c)[3]) \
                 : "r"((a)[0]), "r"((a)[1]), "r"((a)[2]), "r"((a)[3]), "r"(b0), "r"(b1))

__device__ __forceinline__ uint32_t h2u(float a, float b) {
    __half2 h = __floats2half2_rn(a, b);
    return *reinterpret_cast<uint32_t*>(&h);
}

// ---------------------------------------------------------------------------
// Precompute kernels
// ---------------------------------------------------------------------------
__global__ void zero_kernel(float* __restrict__ outAttn) {
    int t = blockIdx.x * blockDim.x + threadIdx.x;
    if (t < Bn * Dn) { outAttn[t] = 0.f; g_ysum[t] = 0.f; }
}

// X: fp32 -> (fp16 hi, fp16 lo residual)
__global__ void convX_kernel(const float* __restrict__ S) {
    size_t base = ((size_t)blockIdx.y * Sn + (size_t)blockIdx.x * 128) * Dn;
    for (int e = threadIdx.x; e < 128 * Dn; e += 256) {
        float v = S[base + e];
        __half h = __float2half_rn(v);
        g_Xh[base + e] = h;
        g_Xl[base + e] = __float2half_rn(v - __half2float(h));
    }
}

// Y: fp32 -> fp16 hi only, fused with column-sum for attention_visual.
__global__ void convY_kernel(const float* __restrict__ S) {
    __shared__ float red[256];
    int b = blockIdx.y;
    size_t base = ((size_t)b * Sn + (size_t)blockIdx.x * 128) * Dn;
    int tid = threadIdx.x;
    float part = 0.f;
    for (int e = tid; e < 128 * Dn; e += 256) {
        float v = S[base + e];
        g_Yh[base + e] = __float2half_rn(v);
        part += v;
    }
    red[tid] = part;
    __syncthreads();
    if (tid < 128) atomicAdd(&g_ysum[b * Dn + tid], red[tid] + red[tid + 128]);
}

// attention_visual: smem-staged GEMV. Coalesced X load -> stride-129 smem
// (bank = (r + d) % 32, conflict-free per-lane) -> thread-per-row dot.
__global__ void visual_kernel(const float* __restrict__ X, float* __restrict__ outVis) {
    extern __shared__ float vs[];      // xs[128*129] then yb[128]
    float* xs = vs;
    float* yb = vs + 128 * 129;
    int b = blockIdx.y, chunk = blockIdx.x, tid = threadIdx.x;

    if (tid < Dn) yb[tid] = g_ysum[b * Dn + tid];
    const float4* src = (const float4*)(X + ((size_t)b * Sn + (size_t)chunk * 128) * Dn);
#pragma unroll
    for (int i = 0; i < 32; i++) {
        int q = tid + i * 128;       // float4 index; 32 per row
        int r = q >> 5, c = q & 31;
        float4 v = src[q];
        float* p = xs + r * 129 + c * 4;
        p[0] = v.x; p[1] = v.y; p[2] = v.z; p[3] = v.w;
    }
    __syncthreads();

    float s = 0.f;
    const float* row = xs + tid * 129;
#pragma unroll 16
    for (int d = 0; d < Dn; d++) s += row[d] * yb[d];
    outVis[(size_t)b * Sn + chunk * 128 + tid] = s * (1.f / Sn);
}

// ---------------------------------------------------------------------------
// Main mma.sync flash-attention kernel.
// 128 threads (4 warps), warp w owns y-rows [w*16, w*16+16) of the CTA tile.
// GEMM inner loops: nbp processed in pairs (4 rotating accumulators, same-C
// dep distance 8 MMAs) with register double-buffered B fragments (LDSM
// latency hidden). Per-accumulator accumulation ORDER identical to R5.
// Smem: Yh @0, X double-buffer @TILE_B (each buf: {Xh, Xl} 2*TILE_B).
// Total dynamic smem = 5*TILE_B = 87040 B -> 2 CTAs/SM.
// ---------------------------------------------------------------------------
__global__ __launch_bounds__(128, 2)
void attn_mma(float* __restrict__ outAttn) {
    extern __shared__ char sm[];
    const uint32_t sb = smem_to_u32(sm);
    const int tid = threadIdx.x;
    const int lane = tid & 31;
    const int wp = tid >> 5;
    const int b = blockIdx.y;
    const int yt = blockIdx.x;

    const uint32_t YHs = sb;
    const uint32_t XBs = sb + TILE_B;   // + buf*(2*TILE_B): {Xh, Xl}

    const __half* gyh = g_Yh + ((size_t)b * Sn + (size_t)yt * TM) * Dn;
    const __half* gxh = g_Xh + (size_t)b * Sn * Dn;
    const __half* gxl = g_Xl + (size_t)b * Sn * Dn;

    // ---- Prologue: load Y tile + X tile 0 ----
    {
        for (int e = tid; e < TM * 16; e += 128) {
            int r = e >> 4, c = e & 15;
            uint32_t o = (uint32_t)(r * RSB + c * 16);
            CP16(YHs + o, gyh + r * Dn + c * 8);
            CP16(XBs + o,          gxh + (size_t)r * Dn + c * 8);
            CP16(XBs + TILE_B + o, gxl + (size_t)r * Dn + c * 8);
        }
        CP_COMMIT();
    }
    CP_WAIT0();
    __syncthreads();

    const int g = lane >> 3;   // ldmatrix address group 0..3
    const int li = lane & 7;

    // ---- A fragments (Yh), persistent in registers ----
    uint32_t Ah[8][4];
    {
        uint32_t abase = (uint32_t)((wp * 16 + (g & 1) * 8 + li) * RSB + (g >> 1) * 16);
#pragma unroll
        for (int kf = 0; kf < 8; kf++) LDM4(Ah[kf], YHs + abase + kf * 32);
    }

    float num[16][4];
#pragma unroll
    for (int nb = 0; nb < 16; nb++)
#pragma unroll
        for (int j = 0; j < 4; j++) num[nb][j] = 0.f;
    float m0 = -1e30f, m1 = -1e30f;
    float den0 = 0.f, den1 = 0.f;

    // GEMM1 (non-trans) B-frag base; GEMM2 (trans) B-frag base
    const uint32_t b1base = (uint32_t)(((g >> 1) * 8 + li) * RSB + (g & 1) * 16);
    const uint32_t b2base = (uint32_t)(((g & 1) * 8 + li) * RSB + (g >> 1) * 16);

#pragma unroll 1
    for (int t = 0; t < NT; t++) {
        CP_WAIT0();
        __syncthreads();
        if (t + 1 < NT) {
            uint32_t dst = XBs + (uint32_t)((t + 1) & 1) * (2 * TILE_B);
            const __half* xh = gxh + (size_t)(t + 1) * TN * Dn;
            const __half* xl = gxl + (size_t)(t + 1) * TN * Dn;
            for (int e = tid; e < TN * 16; e += 128) {
                int r = e >> 4, c = e & 15;
                uint32_t o = (uint32_t)(r * RSB + c * 16);
                CP16(dst + o,          xh + (size_t)r * Dn + c * 8);
                CP16(dst + TILE_B + o, xl + (size_t)r * Dn + c * 8);
            }
        }
        CP_COMMIT();

        const uint32_t XH = XBs + (uint32_t)(t & 1) * (2 * TILE_B);
        const uint32_t XL = XH + TILE_B;

        // ---- GEMM1: S = Yh*Xh + Yh*Xl  (= Yh*X exactly) ----
        // nbp pairs (2ph, 2ph+1); 4 rotating accumulators; B frags double-buffered.
        float Sa[8][4];
#pragma unroll
        for (int nb = 0; nb < 8; nb++)
#pragma unroll
            for (int j = 0; j < 4; j++) Sa[nb][j] = 0.f;

#pragma unroll
        for (int ph = 0; ph < 2; ph++) {
            const uint32_t oA = b1base + (uint32_t)((2 * ph)     * 16 * RSB);
            const uint32_t oB = b1base + (uint32_t)((2 * ph + 1) * 16 * RSB);
            uint32_t bhA[2][4], blA[2][4], bhB[2][4], blB[2][4];
            LDM4(bhA[0], XH + oA); LDM4(blA[0], XL + oA);
            LDM4(bhB[0], XH + oB); LDM4(blB[0], XL + oB);
#pragma unroll
            for (int kf = 0; kf < 8; kf++) {
                const int cur = kf & 1, nxt = cur ^ 1;
                if (kf < 7) {
                    LDM4(bhA[nxt], XH + oA + (kf + 1) * 32);
                    LDM4(blA[nxt], XL + oA + (kf + 1) * 32);
                    LDM4(bhB[nxt], XH + oB + (kf + 1) * 32);
                    LDM4(blB[nxt], XL + oB + (kf + 1) * 32);
                }
                MMA16816(Sa[4 * ph + 0], Ah[kf], bhA[cur][0], bhA[cur][1]);
                MMA16816(Sa[4 * ph + 1], Ah[kf], bhA[cur][2], bhA[cur][3]);
                MMA16816(Sa[4 * ph + 2], Ah[kf], bhB[cur][0], bhB[cur][1]);
                MMA16816(Sa[4 * ph + 3], Ah[kf], bhB[cur][2], bhB[cur][3]);
                MMA16816(Sa[4 * ph + 0], Ah[kf], blA[cur][0], blA[cur][1]);
                MMA16816(Sa[4 * ph + 1], Ah[kf], blA[cur][2], blA[cur][3]);
                MMA16816(Sa[4 * ph + 2], Ah[kf], blB[cur][0], blB[cur][1]);
                MMA16816(Sa[4 * ph + 3], Ah[kf], blB[cur][2], blB[cur][3]);
            }
        }

        // ---- online max + rescale ----
        float t0 = -1e30f, t1 = -1e30f;
#pragma unroll
        for (int nb = 0; nb < 8; nb++) {
            t0 = fmaxf(t0, fmaxf(Sa[nb][0], Sa[nb][1]));
            t1 = fmaxf(t1, fmaxf(Sa[nb][2], Sa[nb][3]));
        }
        t0 = fmaxf(t0, __shfl_xor_sync(0xffffffffu, t0, 1));
        t0 = fmaxf(t0, __shfl_xor_sync(0xffffffffu, t0, 2));
        t1 = fmaxf(t1, __shfl_xor_sync(0xffffffffu, t1, 1));
        t1 = fmaxf(t1, __shfl_xor_sync(0xffffffffu, t1, 2));
        float mn0 = fmaxf(m0, t0), mn1 = fmaxf(m1, t1);
        float f0 = __expf(m0 - mn0), f1 = __expf(m1 - mn1);
        m0 = mn0; m1 = mn1;
        den0 *= f0; den1 *= f1;
#pragma unroll
        for (int nb = 0; nb < 16; nb++) {
            num[nb][0] *= f0; num[nb][1] *= f0;
            num[nb][2] *= f1; num[nb][3] *= f1;
        }

        // ---- exp + pack P as A-fragments for GEMM2 ----
        uint32_t Pa[4][4];
#pragma unroll
        for (int nb = 0; nb < 8; nb++) {
            float p0 = __expf(Sa[nb][0] - m0);
            float p1 = __expf(Sa[nb][1] - m0);
            float p2 = __expf(Sa[nb][2] - m1);
            float p3 = __expf(Sa[nb][3] - m1);
            den0 += p0 + p1;
            den1 += p2 + p3;
            int kg = nb >> 1;
            if ((nb & 1) == 0) { Pa[kg][0] = h2u(p0, p1); Pa[kg][1] = h2u(p2, p3); }
            else               { Pa[kg][2] = h2u(p0, p1); Pa[kg][3] = h2u(p2, p3); }
        }

        // ---- GEMM2: num += P*Xh + P*Xl  (trans ldmatrix B) ----
        // nbp pairs; kg inner with double-buffered B frags.
#pragma unroll
        for (int ph = 0; ph < 4; ph++) {
            const uint32_t oA = b2base + (uint32_t)((2 * ph)     * 32);
            const uint32_t oB = b2base + (uint32_t)((2 * ph + 1) * 32);
            uint32_t bhA[2][4], blA[2][4], bhB[2][4], blB[2][4];
            LDM4T(bhA[0], XH + oA); LDM4T(blA[0], XL + oA);
            LDM4T(bhB[0], XH + oB); LDM4T(blB[0], XL + oB);
#pragma unroll
            for (int kg = 0; kg < 4; kg++) {
                const int cur = kg & 1, nxt = cur ^ 1;
                if (kg < 3) {
                    LDM4T(bhA[nxt], XH + oA + (kg + 1) * 16 * RSB);
                    LDM4T(blA[nxt], XL + oA + (kg + 1) * 16 * RSB);
                    LDM4T(bhB[nxt], XH + oB + (kg + 1) * 16 * RSB);
                    LDM4T(blB[nxt], XL + oB + (kg + 1) * 16 * RSB);
                }
                MMA16816(num[4 * ph + 0], Pa[kg], bhA[cur][0], bhA[cur][1]);
                MMA16816(num[4 * ph + 1], Pa[kg], bhA[cur][2], bhA[cur][3]);
                MMA16816(num[4 * ph + 2], Pa[kg], bhB[cur][0], bhB[cur][1]);
                MMA16816(num[4 * ph + 3], Pa[kg], bhB[cur][2], bhB[cur][3]);
                MMA16816(num[4 * ph + 0], Pa[kg], blA[cur][0], blA[cur][1]);
                MMA16816(num[4 * ph + 1], Pa[kg], blA[cur][2], blA[cur][3]);
                MMA16816(num[4 * ph + 2], Pa[kg], blB[cur][0], blB[cur][1]);
                MMA16816(num[4 * ph + 3], Pa[kg], blB[cur][2], blB[cur][3]);
            }
        }
    }

    // ---- Epilogue ----
    // num index map: nbp = (ph, A/B) -> num[4ph + {0,1}] / num[4ph + {2,3}];
    // d-column of num[q] pair base = ((q>>2)*2 + ((q>>1)&1)) * 16 + (q&1)*8,
    // identical to R5's num[2nbp + j] with nbp = 2*(q>>2) + ((q>>1)&1).
    den0 += __shfl_xor_sync(0xffffffffu, den0, 1);
    den0 += __shfl_xor_sync(0xffffffffu, den0, 2);
    den1 += __shfl_xor_sync(0xffffffffu, den1, 1);
    den1 += __shfl_xor_sync(0xffffffffu, den1, 2);
    float rd0 = 1.f / den0, rd1 = 1.f / den1;

    float* epi = (float*)(sm + TILE_B);   // reuse X buffer region (loop done)
    __syncthreads();
    if (tid < Dn) epi[tid] = 0.f;
    __syncthreads();

    int c0 = 2 * (lane & 3);
#pragma unroll
    for (int q = 0; q < 16; q++) {
        int nbp = 2 * (q >> 2) + ((q >> 1) & 1);
        int nb8 = nbp * 2 + (q & 1);          // original num[] row index
        atomicAdd(&epi[nb8 * 8 + c0],     num[q][0] * rd0 + num[q][2] * rd1);
        atomicAdd(&epi[nb8 * 8 + c0 + 1], num[q][1] * rd0 + num[q][3] * rd1);
    }
    __syncthreads();

    if (tid < Dn) atomicAdd(&outAttn[b * Dn + tid], epi[tid] * (1.f / Sn));
}

// ---------------------------------------------------------------------------
// kernel_launch
// ---------------------------------------------------------------------------
extern "C" void kernel_launch(void* const* d_in, const int* in_sizes, int n_in,
                              void* d_out, int out_size) {
    const float* X = (const float*)d_in[0];  // input_x [B, SX, D]
    const float* Y = (const float*)d_in[1];  // input_y [B, SY, D]
    float* out = (float*)d_out;
    float* outVis  = out;             // [B, SX]
    float* outAttn = out + Bn * Sn;   // [B, D]

    const int vis_smem = (128 * 129 + 128) * sizeof(float);   // 66560
    cudaFuncSetAttribute(attn_mma, cudaFuncAttributeMaxDynamicSharedMemorySize, 5 * TILE_B);
    cudaFuncSetAttribute(visual_kernel, cudaFuncAttributeMaxDynamicSharedMemorySize, vis_smem);

    zero_kernel<<<(Bn * Dn + 255) / 256, 256>>>(outAttn);
    convX_kernel<<<dim3(16, Bn), 256>>>(X);
    convY_kernel<<<dim3(16, Bn), 256>>>(Y);   // also produces g_ysum
    visual_kernel<<<dim3(16, Bn), 128, vis_smem>>>(X, outVis);
    attn_mma<<<dim3(Sn / TM, Bn), 128, 5 * TILE_B>>>(outAttn);
}

// round 15
// speedup vs baseline: 1.1904x; 1.1904x over previous
#include <cuda_runtime.h>
#include <cuda_fp16.h>
#include <math.h>
#include <stdint.h>

// Problem constants
#define Bn 16
#define Sn 2048
#define Dn 128
#define TM 64           // y rows per CTA
#define TN 64           // x cols per tile
#define NT (Sn / TN)    // 32 tiles
#define RSB 272         // smem row stride bytes (136 halves): conflict-free ldmatrix
#define TILE_B (TM * RSB)   // 17408 bytes per 64x128 half tile

// ---------------------------------------------------------------------------
// Global scratch (referenced ONLY from device code)
// ---------------------------------------------------------------------------
__device__ float  g_ysum[Bn * Dn];
__device__ __half g_Yh[Bn * Sn * Dn];
__device__ __half g_Xh[Bn * Sn * Dn];
__device__ __half g_Xl[Bn * Sn * Dn];

// ---------------------------------------------------------------------------
// Helpers
// ---------------------------------------------------------------------------
__device__ __forceinline__ uint32_t smem_to_u32(const void* p) {
    uint32_t a;
    asm("{ .reg .u64 t; cvta.to.shared.u64 t, %1; cvt.u32.u64 %0, t; }" : "=r"(a) : "l"(p));
    return a;
}

#define CP16(dst, src) \
    asm volatile("cp.async.cg.shared.global [%0], [%1], 16;" :: "r"(dst), "l"(src))
#define CP_COMMIT() asm volatile("cp.async.commit_group;" ::: "memory")
#define CP_WAIT0()  asm volatile("cp.async.wait_group 0;" ::: "memory")

#define LDM4(r, a) \
    asm volatile("ldmatrix.sync.aligned.m8n8.x4.shared.b16 {%0,%1,%2,%3}, [%4];" \
                 : "=r"((r)[0]), "=r"((r)[1]), "=r"((r)[2]), "=r"((r)[3]) : "r"(a))
#define LDM4T(r, a) \
    asm volatile("ldmatrix.sync.aligned.m8n8.x4.trans.shared.b16 {%0,%1,%2,%3}, [%4];" \
                 : "=r"((r)[0]), "=r"((r)[1]), "=r"((r)[2]), "=r"((r)[3]) : "r"(a))

#define MMA16816(c, a, b0, b1) \
    asm volatile("mma.sync.aligned.m16n8k16.row.col.f32.f16.f16.f32 " \
                 "{%0,%1,%2,%3},{%4,%5,%6,%7},{%8,%9},{%0,%1,%2,%3};" \
                 : "+f"((c)[0]), "+f"((c)[1]), "+f"((c)[2]), "+f"((c)[3]) \
                 : "r"((a)[0]), "r"((a)[1]), "r"((a)[2]), "r"((a)[3]), "r"(b0), "r"(b1))

__device__ __forceinline__ uint32_t h2u(float a, float b) {
    __half2 h = __floats2half2_rn(a, b);
    return *reinterpret_cast<uint32_t*>(&h);
}

// ---------------------------------------------------------------------------
// Precompute kernels
// ---------------------------------------------------------------------------
__global__ void zero_kernel(float* __restrict__ outAttn) {
    int t = blockIdx.x * blockDim.x + threadIdx.x;
    if (t < Bn * Dn) { outAttn[t] = 0.f; g_ysum[t] = 0.f; }
}

// Y: fp32 -> fp16 hi only, fused with column-sum (g_ysum) for attention_visual.
__global__ void convY_kernel(const float* __restrict__ S) {
    __shared__ float red[256];
    int b = blockIdx.y;
    size_t base = ((size_t)b * Sn + (size_t)blockIdx.x * 128) * Dn;
    int tid = threadIdx.x;
    float part = 0.f;
    for (int e = tid; e < 128 * Dn; e += 256) {
        float v = S[base + e];
        g_Yh[base + e] = __float2half_rn(v);
        part += v;
    }
    red[tid] = part;
    __syncthreads();
    if (tid < 128) atomicAdd(&g_ysum[b * Dn + tid], red[tid] + red[tid + 128]);
}

// X: fp32 -> (fp16 hi, fp16 lo residual) FUSED with attention_visual
// (dot of each x row with g_ysum — convY has completed by launch order).
// 128 threads = 4 warps; warp w handles rows w*32..w*32+31, lane = f4 chunk.
__global__ void convXV_kernel(const float* __restrict__ X, float* __restrict__ outVis) {
    __shared__ float yb[Dn];
    int b = blockIdx.y, chunk = blockIdx.x, tid = threadIdx.x;
    int lane = tid & 31, wp = tid >> 5;
    if (tid < Dn) yb[tid] = g_ysum[b * Dn + tid];
    __syncthreads();

    float4 yv = ((const float4*)yb)[lane];
#pragma unroll 4
    for (int it = 0; it < 32; it++) {
        size_t row = (size_t)b * Sn + chunk * 128 + wp * 32 + it;
        float4 a = ((const float4*)(X + row * Dn))[lane];

        // split to hi/lo fp16 and store (8B per lane, coalesced within warp)
        __half hx = __float2half_rn(a.x), hy = __float2half_rn(a.y);
        __half hz = __float2half_rn(a.z), hw = __float2half_rn(a.w);
        __half2* ph = (__half2*)(g_Xh + row * Dn) + lane * 2;
        __half2* pl = (__half2*)(g_Xl + row * Dn) + lane * 2;
        ph[0] = __halves2half2(hx, hy);
        ph[1] = __halves2half2(hz, hw);
        pl[0] = __halves2half2(__float2half_rn(a.x - __half2float(hx)),
                               __float2half_rn(a.y - __half2float(hy)));
        pl[1] = __halves2half2(__float2half_rn(a.z - __half2float(hz)),
                               __float2half_rn(a.w - __half2float(hw)));

        // visual dot
        float s = a.x * yv.x + a.y * yv.y + a.z * yv.z + a.w * yv.w;
        s += __shfl_xor_sync(0xffffffffu, s, 16);
        s += __shfl_xor_sync(0xffffffffu, s, 8);
        s += __shfl_xor_sync(0xffffffffu, s, 4);
        s += __shfl_xor_sync(0xffffffffu, s, 2);
        s += __shfl_xor_sync(0xffffffffu, s, 1);
        if (lane == 0) outVis[row] = s * (1.f / Sn);
    }
}

// ---------------------------------------------------------------------------
// Main mma.sync flash-attention kernel.
// 128 threads (4 warps), warp w owns y-rows [w*16, w*16+16) of the CTA tile.
// GEMM1: S = Yh*Xh + Yh*Xl (= Yh*X exactly).  GEMM2: num = P*Xh only
// (Xl residual term dropped: row errors are w-weighted fp16 residuals that
// decorrelate across y rows and shrink in the y-mean; ~2e-4 contribution).
// 192 HMMA/warp/tile — HMMA-throughput-bound.
// Smem: Yh @0, X double-buffer @TILE_B (each buf: {Xh, Xl} 2*TILE_B).
// Total dynamic smem = 5*TILE_B = 87040 B -> 2 CTAs/SM.
// ---------------------------------------------------------------------------
__global__ __launch_bounds__(128, 2)
void attn_mma(float* __restrict__ outAttn) {
    extern __shared__ char sm[];
    const uint32_t sb = smem_to_u32(sm);
    const int tid = threadIdx.x;
    const int lane = tid & 31;
    const int wp = tid >> 5;
    const int b = blockIdx.y;
    const int yt = blockIdx.x;

    const uint32_t YHs = sb;
    const uint32_t XBs = sb + TILE_B;   // + buf*(2*TILE_B): {Xh, Xl}

    const __half* gyh = g_Yh + ((size_t)b * Sn + (size_t)yt * TM) * Dn;
    const __half* gxh = g_Xh + (size_t)b * Sn * Dn;
    const __half* gxl = g_Xl + (size_t)b * Sn * Dn;

    // ---- Prologue: load Y tile + X tile 0 ----
    {
        for (int e = tid; e < TM * 16; e += 128) {
            int r = e >> 4, c = e & 15;
            uint32_t o = (uint32_t)(r * RSB + c * 16);
            CP16(YHs + o, gyh + r * Dn + c * 8);
            CP16(XBs + o,          gxh + (size_t)r * Dn + c * 8);
            CP16(XBs + TILE_B + o, gxl + (size_t)r * Dn + c * 8);
        }
        CP_COMMIT();
    }
    CP_WAIT0();
    __syncthreads();

    const int g = lane >> 3;   // ldmatrix address group 0..3
    const int li = lane & 7;

    // ---- A fragments (Yh), persistent in registers ----
    uint32_t Ah[8][4];
    {
        uint32_t abase = (uint32_t)((wp * 16 + (g & 1) * 8 + li) * RSB + (g >> 1) * 16);
#pragma unroll
        for (int kf = 0; kf < 8; kf++) LDM4(Ah[kf], YHs + abase + kf * 32);
    }

    float num[16][4];
#pragma unroll
    for (int nb = 0; nb < 16; nb++)
#pragma unroll
        for (int j = 0; j < 4; j++) num[nb][j] = 0.f;
    float m0 = -1e30f, m1 = -1e30f;
    float den0 = 0.f, den1 = 0.f;

    // GEMM1 (non-trans) B-frag base; GEMM2 (trans) B-frag base
    const uint32_t b1base = (uint32_t)(((g >> 1) * 8 + li) * RSB + (g & 1) * 16);
    const uint32_t b2base = (uint32_t)(((g & 1) * 8 + li) * RSB + (g >> 1) * 16);

#pragma unroll 1
    for (int t = 0; t < NT; t++) {
        CP_WAIT0();
        __syncthreads();
        if (t + 1 < NT) {
            uint32_t dst = XBs + (uint32_t)((t + 1) & 1) * (2 * TILE_B);
            const __half* xh = gxh + (size_t)(t + 1) * TN * Dn;
            const __half* xl = gxl + (size_t)(t + 1) * TN * Dn;
            for (int e = tid; e < TN * 16; e += 128) {
                int r = e >> 4, c = e & 15;
                uint32_t o = (uint32_t)(r * RSB + c * 16);
                CP16(dst + o,          xh + (size_t)r * Dn + c * 8);
                CP16(dst + TILE_B + o, xl + (size_t)r * Dn + c * 8);
            }
        }
        CP_COMMIT();

        const uint32_t XH = XBs + (uint32_t)(t & 1) * (2 * TILE_B);
        const uint32_t XL = XH + TILE_B;

        // ---- GEMM1: S = Yh*Xh + Yh*Xl  (= Yh*X exactly) ----
        float Sa[8][4];
#pragma unroll
        for (int nb = 0; nb < 8; nb++)
#pragma unroll
            for (int j = 0; j < 4; j++) Sa[nb][j] = 0.f;

#pragma unroll
        for (int ph = 0; ph < 2; ph++) {
            const uint32_t oA = b1base + (uint32_t)((2 * ph)     * 16 * RSB);
            const uint32_t oB = b1base + (uint32_t)((2 * ph + 1) * 16 * RSB);
            uint32_t bhA[2][4], blA[2][4], bhB[2][4], blB[2][4];
            LDM4(bhA[0], XH + oA); LDM4(blA[0], XL + oA);
            LDM4(bhB[0], XH + oB); LDM4(blB[0], XL + oB);
#pragma unroll
            for (int kf = 0; kf < 8; kf++) {
                const int cur = kf & 1, nxt = cur ^ 1;
                if (kf < 7) {
                    LDM4(bhA[nxt], XH + oA + (kf + 1) * 32);
                    LDM4(blA[nxt], XL + oA + (kf + 1) * 32);
                    LDM4(bhB[nxt], XH + oB + (kf + 1) * 32);
                    LDM4(blB[nxt], XL + oB + (kf + 1) * 32);
                }
                MMA16816(Sa[4 * ph + 0], Ah[kf], bhA[cur][0], bhA[cur][1]);
                MMA16816(Sa[4 * ph + 1], Ah[kf], bhA[cur][2], bhA[cur][3]);
                MMA16816(Sa[4 * ph + 2], Ah[kf], bhB[cur][0], bhB[cur][1]);
                MMA16816(Sa[4 * ph + 3], Ah[kf], bhB[cur][2], bhB[cur][3]);
                MMA16816(Sa[4 * ph + 0], Ah[kf], blA[cur][0], blA[cur][1]);
                MMA16816(Sa[4 * ph + 1], Ah[kf], blA[cur][2], blA[cur][3]);
                MMA16816(Sa[4 * ph + 2], Ah[kf], blB[cur][0], blB[cur][1]);
                MMA16816(Sa[4 * ph + 3], Ah[kf], blB[cur][2], blB[cur][3]);
            }
        }

        // ---- online max + rescale ----
        float t0 = -1e30f, t1 = -1e30f;
#pragma unroll
        for (int nb = 0; nb < 8; nb++) {
            t0 = fmaxf(t0, fmaxf(Sa[nb][0], Sa[nb][1]));
            t1 = fmaxf(t1, fmaxf(Sa[nb][2], Sa[nb][3]));
        }
        t0 = fmaxf(t0, __shfl_xor_sync(0xffffffffu, t0, 1));
        t0 = fmaxf(t0, __shfl_xor_sync(0xffffffffu, t0, 2));
        t1 = fmaxf(t1, __shfl_xor_sync(0xffffffffu, t1, 1));
        t1 = fmaxf(t1, __shfl_xor_sync(0xffffffffu, t1, 2));
        float mn0 = fmaxf(m0, t0), mn1 = fmaxf(m1, t1);
        float f0 = __expf(m0 - mn0), f1 = __expf(m1 - mn1);
        m0 = mn0; m1 = mn1;
        den0 *= f0; den1 *= f1;
#pragma unroll
        for (int nb = 0; nb < 16; nb++) {
            num[nb][0] *= f0; num[nb][1] *= f0;
            num[nb][2] *= f1; num[nb][3] *= f1;
        }

        // ---- exp + pack P as A-fragments for GEMM2 ----
        uint32_t Pa[4][4];
#pragma unroll
        for (int nb = 0; nb < 8; nb++) {
            float p0 = __expf(Sa[nb][0] - m0);
            float p1 = __expf(Sa[nb][1] - m0);
            float p2 = __expf(Sa[nb][2] - m1);
            float p3 = __expf(Sa[nb][3] - m1);
            den0 += p0 + p1;
            den1 += p2 + p3;
            int kg = nb >> 1;
            if ((nb & 1) == 0) { Pa[kg][0] = h2u(p0, p1); Pa[kg][1] = h2u(p2, p3); }
            else               { Pa[kg][2] = h2u(p0, p1); Pa[kg][3] = h2u(p2, p3); }
        }

        // ---- GEMM2: num += P*Xh  (trans ldmatrix B, hi term only) ----
#pragma unroll
        for (int ph = 0; ph < 4; ph++) {
            const uint32_t oA = b2base + (uint32_t)((2 * ph)     * 32);
            const uint32_t oB = b2base + (uint32_t)((2 * ph + 1) * 32);
            uint32_t bhA[2][4], bhB[2][4];
            LDM4T(bhA[0], XH + oA);
            LDM4T(bhB[0], XH + oB);
#pragma unroll
            for (int kg = 0; kg < 4; kg++) {
                const int cur = kg & 1, nxt = cur ^ 1;
                if (kg < 3) {
                    LDM4T(bhA[nxt], XH + oA + (kg + 1) * 16 * RSB);
                    LDM4T(bhB[nxt], XH + oB + (kg + 1) * 16 * RSB);
                }
                MMA16816(num[4 * ph + 0], Pa[kg], bhA[cur][0], bhA[cur][1]);
                MMA16816(num[4 * ph + 1], Pa[kg], bhA[cur][2], bhA[cur][3]);
                MMA16816(num[4 * ph + 2], Pa[kg], bhB[cur][0], bhB[cur][1]);
                MMA16816(num[4 * ph + 3], Pa[kg], bhB[cur][2], bhB[cur][3]);
            }
        }
    }

    // ---- Epilogue ----
    den0 += __shfl_xor_sync(0xffffffffu, den0, 1);
    den0 += __shfl_xor_sync(0xffffffffu, den0, 2);
    den1 += __shfl_xor_sync(0xffffffffu, den1, 1);
    den1 += __shfl_xor_sync(0xffffffffu, den1, 2);
    float rd0 = 1.f / den0, rd1 = 1.f / den1;

    float* epi = (float*)(sm + TILE_B);   // reuse X buffer region (loop done)
    __syncthreads();
    if (tid < Dn) epi[tid] = 0.f;
    __syncthreads();

    int c0 = 2 * (lane & 3);
#pragma unroll
    for (int q = 0; q < 16; q++) {
        int nbp = 2 * (q >> 2) + ((q >> 1) & 1);
        int nb8 = nbp * 2 + (q & 1);          // d-column pair base = nb8*8
        atomicAdd(&epi[nb8 * 8 + c0],     num[q][0] * rd0 + num[q][2] * rd1);
        atomicAdd(&epi[nb8 * 8 + c0 + 1], num[q][1] * rd0 + num[q][3] * rd1);
    }
    __syncthreads();

    if (tid < Dn) atomicAdd(&outAttn[b * Dn + tid], epi[tid] * (1.f / Sn));
}

// ---------------------------------------------------------------------------
// kernel_launch
// ---------------------------------------------------------------------------
extern "C" void kernel_launch(void* const* d_in, const int* in_sizes, int n_in,
                              void* d_out, int out_size) {
    const float* X = (const float*)d_in[0];  // input_x [B, SX, D]
    const float* Y = (const float*)d_in[1];  // input_y [B, SY, D]
    float* out = (float*)d_out;
    float* outVis  = out;             // [B, SX]
    float* outAttn = out + Bn * Sn;   // [B, D]

    cudaFuncSetAttribute(attn_mma, cudaFuncAttributeMaxDynamicSharedMemorySize, 5 * TILE_B);

    zero_kernel<<<(Bn * Dn + 255) / 256, 256>>>(outAttn);
    convY_kernel<<<dim3(16, Bn), 256>>>(Y);          // g_Yh + g_ysum
    convXV_kernel<<<dim3(16, Bn), 128>>>(X, outVis); // g_Xh/g_Xl + visual
    attn_mma<<<dim3(Sn / TM, Bn), 128, 5 * TILE_B>>>(outAttn);
}